// round 12
// baseline (speedup 1.0000x reference)
#include <cuda_runtime.h>
#include <cstdint>

#define NUM_GRAPHS 512
#define D 128
#define H 256
#define GPB 4             // graphs per block
#define T 1024            // threads per block (32 warps)

// dynamic smem layout (floats)
#define W1_OFF   0            // 32768 floats (128 KB)
#define W2B_OFF  32768        // 16384 floats (2 x 32 KB chunk slots B0,B1)
#define SBUF_OFF 49152        // 4096 floats (16 KB)
#define DYN_FLOATS 53248      // 208 KB
#define W2_CHUNK_FLOATS 8192  // 32 rows x 256 cols
#define W2_CHUNK_BYTES  32768

// ---------------------------------------------------------------------------
__device__ __forceinline__ void facc(float4& a, float4 v) {
    a.x += v.x; a.y += v.y; a.z += v.z; a.w += v.w;
}
__device__ __forceinline__ uint32_t smem_u32(const void* p) {
    uint32_t a;
    asm("{ .reg .u64 t; cvta.to.shared.u64 t, %1; cvt.u32.u64 %0, t; }"
        : "=r"(a) : "l"(p));
    return a;
}
__device__ __forceinline__ void mbar_init(uint32_t mbar, uint32_t cnt) {
    asm volatile("mbarrier.init.shared.b64 [%0], %1;" :: "r"(mbar), "r"(cnt) : "memory");
}
__device__ __forceinline__ void bulk_copy(uint32_t dst, const void* src,
                                          uint32_t bytes, uint32_t mbar) {
    asm volatile(
        "mbarrier.arrive.expect_tx.shared.b64 _, [%0], %1;" :: "r"(mbar), "r"(bytes) : "memory");
    asm volatile(
        "cp.async.bulk.shared::cta.global.mbarrier::complete_tx::bytes [%0], [%1], %2, [%3];"
        :: "r"(dst), "l"(src), "r"(bytes), "r"(mbar) : "memory");
}
__device__ __forceinline__ void mbar_wait(uint32_t mbar) {
    uint32_t done;
    asm volatile(
        "{\n\t.reg .pred p;\n\t"
        "mbarrier.try_wait.parity.acquire.cta.shared::cta.b64 p, [%1], 0;\n\t"
        "selp.b32 %0, 1, 0, p;\n\t}"
        : "=r"(done) : "r"(mbar) : "memory");
    if (!done) {
        asm volatile(
            "{\n\t.reg .pred P1;\n\t"
            "WL_%=:\n\t"
            "mbarrier.try_wait.parity.acquire.cta.shared::cta.b64 P1, [%0], 0, 0x989680;\n\t"
            "@P1 bra.uni WD_%=;\n\t"
            "bra.uni WL_%=;\n\t"
            "WD_%=:\n\t}"
            :: "r"(mbar) : "memory");
    }
}
__device__ __forceinline__ void fence_async() {
    asm volatile("fence.proxy.async.shared::cta;" ::: "memory");
}

// ---------------------------------------------------------------------------
// ONE kernel. Per-block: bounds -> segment-sum of its 4 graphs (contiguous
// rows, batch sorted) -> 2-layer MLP -> head -> scatter. All weights staged
// through smem via cp.async.bulk issued EARLY so their L2 traffic overlaps the
// segsum phase.
__global__ __launch_bounds__(T) void fused_kernel(
        const float4* __restrict__ x4, const int* __restrict__ batch, int N,
        const float* __restrict__ W1, const float* __restrict__ b1,
        const float* __restrict__ W2, const float* __restrict__ b2,
        const float* __restrict__ Wc, const float* __restrict__ bc,
        float* __restrict__ out) {
    extern __shared__ float dsm[];
    float* sW1  = dsm + W1_OFF;
    float* sW2B = dsm + W2B_OFF;    // 2 chunk slots
    float* sBuf = dsm + SBUF_OFF;   // warp partials, then sP

    __shared__ float sS[GPB][D];
    __shared__ float sH[GPB][H];
    __shared__ float sRed[GPB][8];
    __shared__ int   sbound[GPB + 1];
    __shared__ float sv[GPB];
    __shared__ int   sSamp[1024];
    __shared__ alignas(8) unsigned long long mbars[9];  // 0:W1, 1..8:W2 chunks

    const int g0   = blockIdx.x * GPB;
    const int t    = threadIdx.x;
    const int col  = t & (H - 1);
    const int qr   = t >> 8;
    const int lane = t & 31;
    const int warp = t >> 5;

    // ---- t0: init barriers, start W1 + W2 chunks 0,1 streaming NOW ----
    if (t == 0) {
        #pragma unroll
        for (int i = 0; i < 9; i++) mbar_init(smem_u32(&mbars[i]), 1);
        fence_async();
        bulk_copy(smem_u32(sW1), W1, D * H * 4, smem_u32(&mbars[0]));
        bulk_copy(smem_u32(sW2B),                    W2,                      W2_CHUNK_BYTES, smem_u32(&mbars[1]));
        bulk_copy(smem_u32(sW2B + W2_CHUNK_FLOATS),  W2 + W2_CHUNK_FLOATS,    W2_CHUNK_BYTES, smem_u32(&mbars[2]));
    }

    // ---- Bounds round 1: sample batch at 1024 evenly spaced points ----
    {
        int idx = (int)(((long long)t * N) >> 10);
        sSamp[t] = batch[idx];
    }
    __syncthreads();

    // ---- Bounds round 2: warps 0..GPB resolve lb(g0+warp) exactly ----
    if (warp <= GPB) {
        const int v = g0 + warp;
        int cnt = 0;
        #pragma unroll
        for (int k = 0; k < 32; k++)
            cnt += (sSamp[lane + k * 32] < v) ? 1 : 0;
        #pragma unroll
        for (int s = 16; s > 0; s >>= 1)
            cnt += __shfl_down_sync(0xFFFFFFFFu, cnt, s);
        int c = __shfl_sync(0xFFFFFFFFu, cnt, 0);
        int loH = (c > 0)    ? (int)(((long long)(c - 1) * N) >> 10) + 1 : 0;
        int hiH = (c < 1024) ? (int)(((long long)c * N) >> 10) + 1 : N;
        int myc = 0;
        for (int base = loH; base < hiH; base += 128) {
            #pragma unroll
            for (int k = 0; k < 4; k++) {
                int i = base + k * 32 + lane;
                myc += (i < hiH && batch[i] < v) ? 1 : 0;
            }
        }
        #pragma unroll
        for (int s = 16; s > 0; s >>= 1)
            myc += __shfl_down_sync(0xFFFFFFFFu, myc, s);
        if (lane == 0) sbound[warp] = loH + myc;
    }
    __syncthreads();

    // ---- Segment sum (overlaps the weight bulk copies) ----
    {
        const int q   = warp >> 3;
        const int sub = warp & 7;
        const int lo = sbound[q], hi = sbound[q + 1];
        const int len   = hi - lo;
        const int chunk = (len + 7) >> 3;
        const int s = lo + sub * chunk;
        const int e = min(s + chunk, hi);

        float4 a0 = make_float4(0.f, 0.f, 0.f, 0.f);
        float4 a1 = a0, a2 = a0, a3 = a0;
        int r = s;
        #pragma unroll 2
        for (; r + 3 < e; r += 4) {
            float4 v0 = x4[(size_t)(r + 0) * (D / 4) + lane];
            float4 v1 = x4[(size_t)(r + 1) * (D / 4) + lane];
            float4 v2 = x4[(size_t)(r + 2) * (D / 4) + lane];
            float4 v3 = x4[(size_t)(r + 3) * (D / 4) + lane];
            facc(a0, v0); facc(a1, v1); facc(a2, v2); facc(a3, v3);
        }
        for (; r < e; r++)
            facc(a0, x4[(size_t)r * (D / 4) + lane]);
        facc(a0, a1); facc(a2, a3); facc(a0, a2);

        *reinterpret_cast<float4*>(&sBuf[warp * D + lane * 4]) = a0;
    }
    __syncthreads();

    if (t < GPB * D) {
        const int q = t >> 7, c = t & (D - 1);
        float v = 0.f;
        #pragma unroll
        for (int w = 0; w < 8; w++) v += sBuf[(q * 8 + w) * D + c];
        sS[q][c] = v;
    }
    __syncthreads();

    float* sP = sBuf;   // [4 quarters][GPB][H]

    // ---- Layer 1 from smem W1: qr owns k in [qr*32, qr*32+32) ----
    mbar_wait(smem_u32(&mbars[0]));

    float acc[GPB];
    #pragma unroll
    for (int q = 0; q < GPB; q++) acc[q] = 0.f;

    #pragma unroll
    for (int c = 0; c < 8; c++) {
        const int kb = qr * 32 + c * 4;
        float w0 = sW1[(kb + 0) * H + col];
        float w1 = sW1[(kb + 1) * H + col];
        float w2 = sW1[(kb + 2) * H + col];
        float w3 = sW1[(kb + 3) * H + col];
        float4 s0 = *reinterpret_cast<const float4*>(&sS[0][kb]);
        float4 s1 = *reinterpret_cast<const float4*>(&sS[1][kb]);
        float4 s2 = *reinterpret_cast<const float4*>(&sS[2][kb]);
        float4 s3 = *reinterpret_cast<const float4*>(&sS[3][kb]);
        acc[0] = fmaf(s0.x, w0, fmaf(s0.y, w1, fmaf(s0.z, w2, fmaf(s0.w, w3, acc[0]))));
        acc[1] = fmaf(s1.x, w0, fmaf(s1.y, w1, fmaf(s1.z, w2, fmaf(s1.w, w3, acc[1]))));
        acc[2] = fmaf(s2.x, w0, fmaf(s2.y, w1, fmaf(s2.z, w2, fmaf(s2.w, w3, acc[2]))));
        acc[3] = fmaf(s3.x, w0, fmaf(s3.y, w1, fmaf(s3.z, w2, fmaf(s3.w, w3, acc[3]))));
    }
    #pragma unroll
    for (int q = 0; q < GPB; q++) sP[(qr * GPB + q) * H + col] = acc[q];
    __syncthreads();   // everyone done reading sW1 + sP ready

    // t0: W1 region is now free -> stream W2 chunks 2..5 into it
    if (t == 0) {
        fence_async();
        #pragma unroll
        for (int i = 2; i < 6; i++)
            bulk_copy(smem_u32(sW1 + (i - 2) * W2_CHUNK_FLOATS),
                      W2 + i * W2_CHUNK_FLOATS, W2_CHUNK_BYTES,
                      smem_u32(&mbars[1 + i]));
    }

    // combine quarters -> h1 = relu(b1 + Σp) * cnt  (cnt scale = agg2)
    {
        int q = t >> 8, c = t & (H - 1);
        float cnt = (float)(sbound[q + 1] - sbound[q]);
        float h = b1[c] + sP[(0 * GPB + q) * H + c] + sP[(1 * GPB + q) * H + c]
                        + sP[(2 * GPB + q) * H + c] + sP[(3 * GPB + q) * H + c];
        sH[q][c] = fmaxf(h, 0.f) * cnt;
    }
    __syncthreads();

    // ---- Layer 2: 8 chunks of 32 k-rows; qr owns 8 rows per chunk ----
    #pragma unroll
    for (int q = 0; q < GPB; q++) acc[q] = 0.f;

    #pragma unroll
    for (int i = 0; i < 8; i++) {
        const float* wsm =
            (i < 2) ? (sW2B + i * W2_CHUNK_FLOATS)
          : (i < 6) ? (sW1 + (i - 2) * W2_CHUNK_FLOATS)
                    : (sW2B + (i - 6) * W2_CHUNK_FLOATS);
        mbar_wait(smem_u32(&mbars[1 + i]));

        const int kb = i * 32 + qr * 8;        // global k base for this thread
        const int lb = qr * 8;                 // local row in chunk
        #pragma unroll
        for (int c = 0; c < 2; c++) {
            float w0 = wsm[(lb + c * 4 + 0) * H + col];
            float w1 = wsm[(lb + c * 4 + 1) * H + col];
            float w2 = wsm[(lb + c * 4 + 2) * H + col];
            float w3 = wsm[(lb + c * 4 + 3) * H + col];
            float4 s0 = *reinterpret_cast<const float4*>(&sH[0][kb + c * 4]);
            float4 s1 = *reinterpret_cast<const float4*>(&sH[1][kb + c * 4]);
            float4 s2 = *reinterpret_cast<const float4*>(&sH[2][kb + c * 4]);
            float4 s3 = *reinterpret_cast<const float4*>(&sH[3][kb + c * 4]);
            acc[0] = fmaf(s0.x, w0, fmaf(s0.y, w1, fmaf(s0.z, w2, fmaf(s0.w, w3, acc[0]))));
            acc[1] = fmaf(s1.x, w0, fmaf(s1.y, w1, fmaf(s1.z, w2, fmaf(s1.w, w3, acc[1]))));
            acc[2] = fmaf(s2.x, w0, fmaf(s2.y, w1, fmaf(s2.z, w2, fmaf(s2.w, w3, acc[2]))));
            acc[3] = fmaf(s3.x, w0, fmaf(s3.y, w1, fmaf(s3.z, w2, fmaf(s3.w, w3, acc[3]))));
        }

        // Recycle B slots: after chunk0 (B0) fully consumed, stream chunk 6
        // into B0; after chunk1 (B1), stream chunk 7 into B1.
        if (i == 0 || i == 1) {
            __syncthreads();   // all threads done reading this B slot
            if (t == 0) {
                fence_async();
                bulk_copy(smem_u32(sW2B + i * W2_CHUNK_FLOATS),
                          W2 + (6 + i) * W2_CHUNK_FLOATS, W2_CHUNK_BYTES,
                          smem_u32(&mbars[7 + i]));
            }
        }
    }
    #pragma unroll
    for (int q = 0; q < GPB; q++) sP[(qr * GPB + q) * H + col] = acc[q];
    __syncthreads();

    // ---- Head: h2 = relu(b2 + Σp); c = Σ_col h2*Wc; softplus-sigmoid ----
    {
        int q = t >> 8, c = t & (H - 1);
        float h = b2[c] + sP[(0 * GPB + q) * H + c] + sP[(1 * GPB + q) * H + c]
                        + sP[(2 * GPB + q) * H + c] + sP[(3 * GPB + q) * H + c];
        float v = fmaxf(h, 0.f) * Wc[c];
        #pragma unroll
        for (int s = 16; s > 0; s >>= 1)
            v += __shfl_down_sync(0xFFFFFFFFu, v, s);
        if (lane == 0) sRed[q][warp & 7] = v;
    }
    __syncthreads();

    if (t < GPB) {
        float c = bc[0];
        #pragma unroll
        for (int w = 0; w < 8; w++) c += sRed[t][w];
        float sp = fmaxf(c, 0.f) + log1pf(expf(-fabsf(c)));
        sv[t] = sp / (1.f + sp);
    }
    __syncthreads();

    // ---- Scatter over this block's contiguous node range ----
    const int lo = sbound[0], hi = sbound[GPB];
    for (int n = lo + t; n < hi; n += T)
        out[n] = sv[batch[n] - g0];
}

// ---------------------------------------------------------------------------
extern "C" void kernel_launch(void* const* d_in, const int* in_sizes, int n_in,
                              void* d_out, int out_size) {
    const float* x     = (const float*)d_in[0];
    const int*   batch = (const int*)d_in[1];
    const float* W1    = (const float*)d_in[2];
    const float* b1    = (const float*)d_in[3];
    const float* W2    = (const float*)d_in[4];
    const float* b2    = (const float*)d_in[5];
    const float* Wc    = (const float*)d_in[6];
    const float* bc    = (const float*)d_in[7];
    float*       out   = (float*)d_out;

    const int N = in_sizes[1];
    const int dynBytes = DYN_FLOATS * 4;   // 208 KB

    cudaFuncSetAttribute(fused_kernel,
                         cudaFuncAttributeMaxDynamicSharedMemorySize, dynBytes);

    fused_kernel<<<NUM_GRAPHS / GPB, T, dynBytes>>>(
        reinterpret_cast<const float4*>(x), batch, N,
        W1, b1, W2, b2, Wc, bc, out);
}